// round 2
// baseline (speedup 1.0000x reference)
#include <cuda_runtime.h>
#include <cstdint>

// NODE forest: B=1048576 samples, 64 inputs, 8 trees x depth 6, TREE_DIM=2.
// Per sample: 48 fp32 dots (len 64) -> XLA-faithful sigmoid>0.5 bits ->
// leaf idx per tree -> folded (leaf_values x fc_w) table lookup -> sum + fc_b.
//
// Numerics matched to reference:
//   z = fl(sequential-FMA dot over i=0..63) + b     (bias AFTER dot)
//   bit = fl(0.5 + 0.25*z) > 0.5                    (XLA logistic-via-tanh rounding)
//
// Thread tiling: 256 threads/block = 64 sample-groups (4 samples each)
//                x 4 selector-groups (12 selectors = 6 f32x2-packed pairs).

#define SPB 256          // samples per block
#define NBLK 4096        // 1048576 / 256

// ---- shared layout (bytes) ----
// Wp  : 24*64 u64  = 12288   @ 0
// bp  : 24 u64     = 192     @ 12288
// xs  : 256*65 f32 = 66560   @ 12480
// tbl : 512 float2 = 4096    @ 79040
#define SMEM_BYTES 83136

static __device__ __forceinline__ unsigned long long pack2f(float lo, float hi) {
    unsigned long long r;
    asm("mov.b64 %0, {%1, %2};" : "=l"(r) : "f"(lo), "f"(hi));
    return r;
}
static __device__ __forceinline__ void unpack2f(unsigned long long v, float& lo, float& hi) {
    asm("mov.b64 {%0, %1}, %2;" : "=f"(lo), "=f"(hi) : "l"(v));
}
// packed fp32x2 FMA: d.lo += a.lo*b.lo ; d.hi += a.hi*b.hi
static __device__ __forceinline__ void ffma2(unsigned long long& d,
                                             unsigned long long a,
                                             unsigned long long b) {
    asm("fma.rn.f32x2 %0, %1, %2, %0;" : "+l"(d) : "l"(a), "l"(b));
}
// packed fp32x2 add (per-lane round-to-nearest, identical to scalar fadd.rn)
static __device__ __forceinline__ void fadd2(unsigned long long& d,
                                             unsigned long long a) {
    asm("add.rn.f32x2 %0, %0, %1;" : "+l"(d) : "l"(a));
}
// XLA-faithful decision: sigmoid(z) > 0.5 with logistic = 0.5 + 0.5*tanh(0.5z),
// which for the decisive near-zero band is fl(0.5 + 0.25*z) > 0.5.
static __device__ __forceinline__ int xla_bit(float z) {
    return __fadd_rn(0.5f, __fmul_rn(0.25f, z)) > 0.5f;
}

__global__ __launch_bounds__(256, 2)
void node_forest_kernel(const float*  __restrict__ x,      // [B,64]
                        const float*  __restrict__ Wsel,   // [8,6,64] = [48,64]
                        const float*  __restrict__ bsel,   // [48]
                        const float*  __restrict__ leafv,  // [8,64,2]
                        const float*  __restrict__ fcw,    // [2,16]
                        const float*  __restrict__ fcb,    // [2]
                        float2*       __restrict__ out)    // [B] float2
{
    extern __shared__ unsigned char smem[];
    unsigned long long* Wp  = (unsigned long long*)(smem);
    unsigned long long* bp  = (unsigned long long*)(smem + 12288);
    float*              xs  = (float*)(smem + 12480);
    float2*             tbl = (float2*)(smem + 79040);

    const int tid  = threadIdx.x;
    const int base = blockIdx.x * SPB;

    // ---- stage x tile coalesced into shared (row stride 65 floats) ----
    const float4* xg = (const float4*)x + (size_t)blockIdx.x * (SPB * 16);
    #pragma unroll
    for (int it = 0; it < 16; ++it) {
        int f = tid + it * 256;          // 0..4095 float4 index within tile
        float4 v = xg[f];
        int s = f >> 4;                  // sample within block
        int c = (f & 15) << 2;           // float offset within row
        float* d = xs + s * 65 + c;
        d[0] = v.x; d[1] = v.y; d[2] = v.z; d[3] = v.w;
    }

    // ---- pack W selector pairs: Wp[P][i] = {W[2P][i], W[2P+1][i]} ----
    for (int e = tid; e < 1536; e += 256) {
        int P = e >> 6, i = e & 63;
        Wp[(P << 6) + i] = pack2f(Wsel[(2 * P) * 64 + i],
                                  Wsel[(2 * P + 1) * 64 + i]);
    }
    if (tid < 24) bp[tid] = pack2f(bsel[2 * tid], bsel[2 * tid + 1]);

    // ---- fold leaf_values with fc_w: tbl[t*64+leaf] = contribution to (y0,y1) ----
    for (int e = tid; e < 512; e += 256) {
        int t = e >> 6, leaf = e & 63;
        float l0 = leafv[t * 128 + leaf * 2 + 0];
        float l1 = leafv[t * 128 + leaf * 2 + 1];
        tbl[e] = make_float2(l0 * fcw[t * 2]      + l1 * fcw[t * 2 + 1],
                             l0 * fcw[16 + t * 2] + l1 * fcw[16 + t * 2 + 1]);
    }
    __syncthreads();

    const int gq = tid & 3;     // selector group: pairs [6*gq, 6*gq+6) = trees 2gq, 2gq+1
    const int sg = tid >> 2;    // sample group: samples [4*sg, 4*sg+4)
    const int p0 = gq * 6;

    // dot accumulators start at ZERO (bias added after, matching reference)
    unsigned long long acc[6][4];
    #pragma unroll
    for (int p = 0; p < 6; ++p)
        #pragma unroll
        for (int j = 0; j < 4; ++j) acc[p][j] = 0ull;

    const float* xr = xs + sg * 4 * 65;
    const unsigned long long* wbase = Wp + (p0 << 6);

    // strictly ascending i, single sequential FMA chain per logit (Eigen gebp order)
    #pragma unroll 4
    for (int i = 0; i < 64; i += 2) {
        unsigned long long xd[4][2];
        #pragma unroll
        for (int j = 0; j < 4; ++j) {
            float a0 = xr[j * 65 + i];
            float a1 = xr[j * 65 + i + 1];
            xd[j][0] = pack2f(a0, a0);
            xd[j][1] = pack2f(a1, a1);
        }
        #pragma unroll
        for (int p = 0; p < 6; ++p) {
            ulonglong2 w = *(const ulonglong2*)(wbase + (p << 6) + i);
            #pragma unroll
            for (int j = 0; j < 4; ++j) {
                ffma2(acc[p][j], w.x, xd[j][0]);
                ffma2(acc[p][j], w.y, xd[j][1]);
            }
        }
    }

    // ---- add bias (packed, per-lane fadd.rn), bits -> leaf idx -> gather ----
    #pragma unroll
    for (int p = 0; p < 6; ++p) {
        unsigned long long b2 = bp[p0 + p];
        #pragma unroll
        for (int j = 0; j < 4; ++j) fadd2(acc[p][j], b2);
    }

    const float fb0 = fcb[0], fb1 = fcb[1];
    #pragma unroll
    for (int j = 0; j < 4; ++j) {
        int leafA = 0, leafB = 0;
        #pragma unroll
        for (int p = 0; p < 3; ++p) {
            float l, h;
            unpack2f(acc[p][j], l, h);           // sels d=2p, 2p+1 of tree 2gq
            if (xla_bit(l)) leafA |= (32 >> (2 * p));
            if (xla_bit(h)) leafA |= (16 >> (2 * p));
            unpack2f(acc[p + 3][j], l, h);       // tree 2gq+1
            if (xla_bit(l)) leafB |= (32 >> (2 * p));
            if (xla_bit(h)) leafB |= (16 >> (2 * p));
        }
        float2 ta = tbl[(2 * gq)     * 64 + leafA];
        float2 tb = tbl[(2 * gq + 1) * 64 + leafB];
        float s0 = ta.x + tb.x;
        float s1 = ta.y + tb.y;
        // reduce across the 4 selector-group lanes (consecutive lanes, bits 0-1)
        s0 += __shfl_xor_sync(0xffffffffu, s0, 1);
        s1 += __shfl_xor_sync(0xffffffffu, s1, 1);
        s0 += __shfl_xor_sync(0xffffffffu, s0, 2);
        s1 += __shfl_xor_sync(0xffffffffu, s1, 2);
        if (gq == 0) {
            out[base + sg * 4 + j] = make_float2(s0 + fb0, s1 + fb1);
        }
    }
}

extern "C" void kernel_launch(void* const* d_in, const int* in_sizes, int n_in,
                              void* d_out, int out_size) {
    (void)in_sizes; (void)n_in; (void)out_size;
    cudaFuncSetAttribute(node_forest_kernel,
                         cudaFuncAttributeMaxDynamicSharedMemorySize, SMEM_BYTES);
    node_forest_kernel<<<NBLK, 256, SMEM_BYTES>>>(
        (const float*)d_in[0],   // x
        (const float*)d_in[1],   // W_sel
        (const float*)d_in[2],   // b_sel
        (const float*)d_in[3],   // leaf_values
        (const float*)d_in[4],   // fc_w
        (const float*)d_in[5],   // fc_b
        (float2*)d_out);
}

// round 3
// speedup vs baseline: 2.6139x; 2.6139x over previous
#include <cuda_runtime.h>
#include <cstdint>

// NODE forest: B=1048576, 64 inputs, 8 trees x depth 6, TREE_DIM=2.
// R2: shared-crossbar fixes — padded W stride (66 u64, kills 4-way bank
// conflict across gq), float4 x loads with per-sample-group column rotation,
// coalesced float2 output stores. Target: FFMA2-pipe-bound.
//
// Numerics (bit-faithful to reference):
//   z = fl(sequential ascending-i FMA dot) + b   (bias AFTER dot)
//   bit = fl(0.5 + 0.25*z) > 0.5                 (XLA logistic rounding)

#define SPB 256
#define NBLK 4096

// ---- shared layout (bytes) ----
// Wp  : 24 rows x 66 u64 = 12672  @ 0
// bp  : 24 u64           = 192    @ 12672
// xs  : 256*64 f32       = 65536  @ 12864   (swizzled float4 columns)
// tbl : 512 float2       = 4096   @ 78400
#define WP_STRIDE 66
#define XS_OFF   12864
#define TBL_OFF  78400
#define SMEM_BYTES 82496

static __device__ __forceinline__ unsigned long long pack2f(float lo, float hi) {
    unsigned long long r;
    asm("mov.b64 %0, {%1, %2};" : "=l"(r) : "f"(lo), "f"(hi));
    return r;
}
static __device__ __forceinline__ void unpack2f(unsigned long long v, float& lo, float& hi) {
    asm("mov.b64 {%0, %1}, %2;" : "=f"(lo), "=f"(hi) : "l"(v));
}
static __device__ __forceinline__ void ffma2(unsigned long long& d,
                                             unsigned long long a,
                                             unsigned long long b) {
    asm("fma.rn.f32x2 %0, %1, %2, %0;" : "+l"(d) : "l"(a), "l"(b));
}
static __device__ __forceinline__ void fadd2(unsigned long long& d,
                                             unsigned long long a) {
    asm("add.rn.f32x2 %0, %0, %1;" : "+l"(d) : "l"(a));
}
static __device__ __forceinline__ int xla_bit(float z) {
    return __fadd_rn(0.5f, __fmul_rn(0.25f, z)) > 0.5f;
}

__global__ __launch_bounds__(256, 2)
void node_forest_kernel(const float*  __restrict__ x,      // [B,64]
                        const float*  __restrict__ Wsel,   // [48,64]
                        const float*  __restrict__ bsel,   // [48]
                        const float*  __restrict__ leafv,  // [8,64,2]
                        const float*  __restrict__ fcw,    // [2,16]
                        const float*  __restrict__ fcb,    // [2]
                        float2*       __restrict__ out)    // [B] float2
{
    extern __shared__ unsigned char smem[];
    unsigned long long* Wp  = (unsigned long long*)(smem);
    unsigned long long* bp  = (unsigned long long*)(smem + 12672);
    float*              xs  = (float*)(smem + XS_OFF);
    float2*             tbl = (float2*)(smem + TBL_OFF);

    const int tid  = threadIdx.x;
    const int base = blockIdx.x * SPB;

    // ---- stage x tile: float4, column-rotated by sample-group ----
    // sample s, float4-column c stored at slot ((c + (s>>2)) & 15)
    const float4* xg = (const float4*)x + (size_t)blockIdx.x * (SPB * 16);
    #pragma unroll
    for (int it = 0; it < 16; ++it) {
        int f = tid + it * 256;          // float4 index within tile
        float4 v = xg[f];
        int s = f >> 4;
        int c = f & 15;
        int slot = (c + (s >> 2)) & 15;
        *(float4*)(xs + s * 64 + slot * 4) = v;
    }

    // ---- pack W selector pairs, padded stride ----
    for (int e = tid; e < 1536; e += 256) {
        int P = e >> 6, i = e & 63;
        Wp[P * WP_STRIDE + i] = pack2f(Wsel[(2 * P) * 64 + i],
                                       Wsel[(2 * P + 1) * 64 + i]);
    }
    if (tid < 24) bp[tid] = pack2f(bsel[2 * tid], bsel[2 * tid + 1]);

    // ---- fold leaf_values with fc_w ----
    for (int e = tid; e < 512; e += 256) {
        int t = e >> 6, leaf = e & 63;
        float l0 = leafv[t * 128 + leaf * 2 + 0];
        float l1 = leafv[t * 128 + leaf * 2 + 1];
        tbl[e] = make_float2(l0 * fcw[t * 2]      + l1 * fcw[t * 2 + 1],
                             l0 * fcw[16 + t * 2] + l1 * fcw[16 + t * 2 + 1]);
    }
    __syncthreads();

    const int gq = tid & 3;     // selector group: trees 2gq, 2gq+1 (6 pairs)
    const int sg = tid >> 2;    // sample group: samples 4*sg .. 4*sg+3
    const int p0 = gq * 6;

    unsigned long long acc[6][4];
    #pragma unroll
    for (int p = 0; p < 6; ++p)
        #pragma unroll
        for (int j = 0; j < 4; ++j) acc[p][j] = 0ull;

    const float* xr = xs + sg * 4 * 64;
    const unsigned long long* wbase = Wp + p0 * WP_STRIDE;

    // strictly ascending i per accumulator chain
    #pragma unroll 2
    for (int i4 = 0; i4 < 16; ++i4) {
        const int i = i4 * 4;
        const int slot = ((i4 + sg) & 15) * 4;
        unsigned long long xd[4][4];
        #pragma unroll
        for (int j = 0; j < 4; ++j) {
            float4 v = *(const float4*)(xr + j * 64 + slot);
            xd[j][0] = pack2f(v.x, v.x);
            xd[j][1] = pack2f(v.y, v.y);
            xd[j][2] = pack2f(v.z, v.z);
            xd[j][3] = pack2f(v.w, v.w);
        }
        #pragma unroll
        for (int p = 0; p < 6; ++p) {
            ulonglong2 w01 = *(const ulonglong2*)(wbase + p * WP_STRIDE + i);
            ulonglong2 w23 = *(const ulonglong2*)(wbase + p * WP_STRIDE + i + 2);
            #pragma unroll
            for (int j = 0; j < 4; ++j) {
                ffma2(acc[p][j], w01.x, xd[j][0]);
                ffma2(acc[p][j], w01.y, xd[j][1]);
                ffma2(acc[p][j], w23.x, xd[j][2]);
                ffma2(acc[p][j], w23.y, xd[j][3]);
            }
        }
    }

    // ---- bias, bits -> leaf idx -> folded-table gather, quad reduce ----
    #pragma unroll
    for (int p = 0; p < 6; ++p) {
        unsigned long long b2 = bp[p0 + p];
        #pragma unroll
        for (int j = 0; j < 4; ++j) fadd2(acc[p][j], b2);
    }

    const float fb0 = fcb[0], fb1 = fcb[1];
    float keep0 = 0.f, keep1 = 0.f;
    #pragma unroll
    for (int j = 0; j < 4; ++j) {
        int leafA = 0, leafB = 0;
        #pragma unroll
        for (int p = 0; p < 3; ++p) {
            float l, h;
            unpack2f(acc[p][j], l, h);
            if (xla_bit(l)) leafA |= (32 >> (2 * p));
            if (xla_bit(h)) leafA |= (16 >> (2 * p));
            unpack2f(acc[p + 3][j], l, h);
            if (xla_bit(l)) leafB |= (32 >> (2 * p));
            if (xla_bit(h)) leafB |= (16 >> (2 * p));
        }
        float2 ta = tbl[(2 * gq)     * 64 + leafA];
        float2 tb = tbl[(2 * gq + 1) * 64 + leafB];
        float s0 = ta.x + tb.x;
        float s1 = ta.y + tb.y;
        s0 += __shfl_xor_sync(0xffffffffu, s0, 1);
        s1 += __shfl_xor_sync(0xffffffffu, s1, 1);
        s0 += __shfl_xor_sync(0xffffffffu, s0, 2);
        s1 += __shfl_xor_sync(0xffffffffu, s1, 2);
        if (j == gq) { keep0 = s0 + fb0; keep1 = s1 + fb1; }
    }
    // coalesced: lane (sg,gq) stores sample 4*sg+gq
    out[base + sg * 4 + gq] = make_float2(keep0, keep1);
}

extern "C" void kernel_launch(void* const* d_in, const int* in_sizes, int n_in,
                              void* d_out, int out_size) {
    (void)in_sizes; (void)n_in; (void)out_size;
    cudaFuncSetAttribute(node_forest_kernel,
                         cudaFuncAttributeMaxDynamicSharedMemorySize, SMEM_BYTES);
    node_forest_kernel<<<NBLK, 256, SMEM_BYTES>>>(
        (const float*)d_in[0],   // x
        (const float*)d_in[1],   // W_sel
        (const float*)d_in[2],   // b_sel
        (const float*)d_in[3],   // leaf_values
        (const float*)d_in[4],   // fc_w
        (const float*)d_in[5],   // fc_b
        (float2*)d_out);
}